// round 17
// baseline (speedup 1.0000x reference)
#include <cuda_runtime.h>

// Algebraic feature expansion:
//   out[r, 0:16]    = x[r, :]
//   out[r, 16:136]  = all pair products  x[i]*x[j],       i<j   (lexicographic)
//   out[r, 136:696] = all triple products x[i]*x[j]*x[k], i<j<k (lexicographic)
//
// R11 emitter structure (known-good codegen: scalar emit, ~22 bulk flush
// events) + per-row phase-aligned store windows via a 64-column ring:
//   row stride 2784B = 96 mod 128. Row rr uses chunk boundaries at columns
//   = 8*(rr&3) (mod 32), making every chunk's byte base = 0 mod 128:
//       96*rr + 32*(rr&3) = 128*(rr&3) + 384*(rr>>2) = 0 (mod 128).
//   Flush events every 32 emits (t = 64,96,...,672): row rr stores window
//   [t-64+8p, t-32+8p), p = rr&3 -- one aligned 128B line per row per event.
//   Heads ([0,8p), line-interior) at t=32; last chunks + tails in cleanup.
// Ring: 64 slots/thread, slot = col & 63, PADF = 65 keeps emit (col-major
// write) and flush (row-major read) bank-conflict-free.

#define N_COLS    16
#define OUT_COLS  696          // 16 + 120 + 560
#define BLOCK     256
#define PADF      65           // 64 + 1; (65*r + c) % 32 == (r + c) % 32
#define SMEM_BYTES ((BLOCK / 32) * 32 * PADF * 4)   // 66560

__global__ __launch_bounds__(BLOCK)
void algebraic_kernel(const float* __restrict__ x, float* __restrict__ out) {
    extern __shared__ float sh[];

    const int lane  = threadIdx.x & 31;
    const int warp  = threadIdx.x >> 5;
    const int row   = blockIdx.x * BLOCK + threadIdx.x;      // this thread's row
    const int wrow0 = blockIdx.x * BLOCK + (warp << 5);      // first row of this warp

    // Load the 16-element row as 4x float4.
    float v[N_COLS];
    {
        const float4* xr = reinterpret_cast<const float4*>(x + (size_t)row * N_COLS);
        float4 a0 = xr[0], a1 = xr[1], a2 = xr[2], a3 = xr[3];
        v[0]  = a0.x; v[1]  = a0.y; v[2]  = a0.z; v[3]  = a0.w;
        v[4]  = a1.x; v[5]  = a1.y; v[6]  = a1.z; v[7]  = a1.w;
        v[8]  = a2.x; v[9]  = a2.y; v[10] = a2.z; v[11] = a2.w;
        v[12] = a3.x; v[13] = a3.y; v[14] = a3.z; v[15] = a3.w;
    }

    float* s      = sh + warp * (32 * PADF);  // this warp's 32 x 64 ring tile
    float* myslot = s + lane * PADF;          // this thread's ring row
    float* outw   = out + (size_t)wrow0 * OUT_COLS;

    int pos = 0;   // columns emitted (constant-folds under full unroll)

    // General event at t (multiple of 32, 64 <= t <= 672): per row rr flush
    // window [t-64+8p, t-32+8p), p = rr&3. Single aligned 128B line per store.
#define FLUSH(t)                                                              \
    do {                                                                      \
        __syncwarp();                                                         \
        _Pragma("unroll")                                                     \
        for (int rr_ = 0; rr_ < 32; ++rr_) {                                  \
            const int col_ = (t) - 64 + 8 * (rr_ & 3) + lane;                 \
            __stcs(outw + rr_ * OUT_COLS + col_, s[rr_ * PADF + (col_ & 63)]); \
        }                                                                     \
        __syncwarp();                                                         \
    } while (0)

    // Heads event at t=32: row rr stores [0, 8p) (p>=1), within-line spans.
#define HEADS()                                                               \
    do {                                                                      \
        __syncwarp();                                                         \
        _Pragma("unroll")                                                     \
        for (int rr_ = 0; rr_ < 32; ++rr_) {                                  \
            const int p_ = rr_ & 3;                                           \
            if (p_ != 0 && lane < 8 * p_)                                     \
                __stcs(outw + rr_ * OUT_COLS + lane, s[rr_ * PADF + lane]);   \
        }                                                                     \
        __syncwarp();                                                         \
    } while (0)

#define EMIT(val)                                                             \
    do {                                                                      \
        myslot[pos & 63] = (val);                                             \
        ++pos;                                                                \
        if (pos == 32) HEADS();                                               \
        else if (pos >= 64 && pos <= 672 && (pos & 31) == 0) FLUSH(pos);      \
    } while (0)

    // ---- singles: columns 0..15 ----
#pragma unroll
    for (int i = 0; i < N_COLS; ++i) {
        EMIT(v[i]);
    }

    // ---- pairs: columns 16..135, lexicographic (i<j) ----
#pragma unroll
    for (int i = 0; i < N_COLS; ++i) {
#pragma unroll
        for (int j = i + 1; j < N_COLS; ++j) {
            EMIT(v[i] * v[j]);
        }
    }

    // ---- triples: columns 136..695, lexicographic (i<j<k) ----
#pragma unroll
    for (int i = 0; i < N_COLS; ++i) {
#pragma unroll
        for (int j = i + 1; j < N_COLS; ++j) {
            float p = v[i] * v[j];
#pragma unroll
            for (int k = j + 1; k < N_COLS; ++k) {
                EMIT(p * v[k]);
            }
        }
    }

    // Cleanup (pos == 696, ring holds cols [632, 696)). Per row rr (p = rr&3):
    //   last chunk [640+8p, 672+8p)  (aligned 128B line)
    //   tail       [672+8p, 696), width 24-8p (single line, aligned base)
    {
        __syncwarp();
#pragma unroll
        for (int rr_ = 0; rr_ < 32; ++rr_) {
            const int p_   = rr_ & 3;
            const int col_ = 640 + 8 * p_ + lane;
            __stcs(outw + rr_ * OUT_COLS + col_, s[rr_ * PADF + (col_ & 63)]);
            if (lane < 24 - 8 * p_) {
                const int c2_ = 672 + 8 * p_ + lane;
                __stcs(outw + rr_ * OUT_COLS + c2_, s[rr_ * PADF + (c2_ & 63)]);
            }
        }
    }
#undef EMIT
#undef HEADS
#undef FLUSH
}

extern "C" void kernel_launch(void* const* d_in, const int* in_sizes, int n_in,
                              void* d_out, int out_size) {
    const float* x = (const float*)d_in[0];
    float* out = (float*)d_out;
    const int batch = in_sizes[0] / N_COLS;   // 262144
    const int grid = (batch + BLOCK - 1) / BLOCK;
    cudaFuncSetAttribute(algebraic_kernel,
                         cudaFuncAttributeMaxDynamicSharedMemorySize, SMEM_BYTES);
    algebraic_kernel<<<grid, BLOCK, SMEM_BYTES>>>(x, out);
}